// round 14
// baseline (speedup 1.0000x reference)
#include <cuda_runtime.h>
#include <cuda_fp16.h>
#include <math.h>

#define NB 4
#define H  512
#define W  360
#define D  512

// Padded, pair-packed, fp16 filtered sinogram, stored as uint4 entries so the
// base is guaranteed 16-byte aligned (LDG.128/STG.128 legality).
// Entry (w, p) holds rows (p-128) and (p-127) of angle w for all 4 batches:
//   halves[0..3] = F[p-128][b],  halves[4..7] = F[p-127][b]   (16 bytes)
// Rows outside [0,512) are zero (guard), which reproduces the reference's
// boundary semantics exactly (zero weight <=> out-of-range index).
#define PADROWS 768
__device__ uint4 g_F2[(size_t)W * PADROWS];
// Per-angle projection coefficients: py = 255.5 + (j-256)*A + (i-256)*B
__device__ float2 g_AB[W];

// ---------------------------------------------------------------------------
// Kernel 1: circular ramp filtering (unchanged from R12 WIN).
//   F[b][w][h] = sum_k hG[k] * radon[b][(h + 257 + k) & 511][w]
// Grid: 360 blocks of 128 threads. Block = (batch, group of 4 angles).
// Block 0 additionally computes the fp64-accurate angle table.
//
// Guard-zero ownership (each angle column is written by 4 batch-blocks):
//  - entries 0..126 and 640..767 are PURE guard: identical 16B zeros from
//    every batch block -> benign race.
//  - entries 127/639 are MIXED: each batch block zeroes only its own guard
//    half-slots, so every half-slot has exactly one writer.
// ---------------------------------------------------------------------------
__global__ __launch_bounds__(128) void filter_kernel(
    const float* __restrict__ radon,  // [NB][H][W]
    const float* __restrict__ hG)     // [H]
{
    __shared__ float sh_x[4][1032];   // per-angle rotated/duplicated column
    __shared__ float sh_h[512];

    const int tid   = threadIdx.x;
    const int batch = blockIdx.x / (W / 4);
    const int w0    = (blockIdx.x % (W / 4)) * 4;

    // Angle table (block 0 only): th = pi*w/360 in fp64,
    // A = cos(th)*511/512, B = -sin(th)*511/512.
    if (blockIdx.x == 0) {
        for (int k = tid; k < W; k += 128) {
            double s, c;
            sincospi((double)k / 360.0, &s, &c);
            const double sc = 511.0 / 512.0;   // exact
            g_AB[k] = make_float2((float)(c * sc), (float)(-s * sc));
        }
    }

    // Guard zeroing per the ownership scheme above.
    {
        const uint4 z = make_uint4(0, 0, 0, 0);
        const __half hz = __float2half(0.0f);
        #pragma unroll
        for (int a = 0; a < 4; a++) {
            uint4* e = g_F2 + (size_t)(w0 + a) * PADROWS;
            __half* col = reinterpret_cast<__half*>(e);
            if (tid < 127) e[tid] = z;                               // 0..126
            for (int p = 640 + tid; p < PADROWS; p += 128) e[p] = z; // 640..767
            if (tid == a) {              // one thread per angle does the 2 halves
                col[127 * 8 + batch]     = hz;   // row -1 half
                col[639 * 8 + 4 + batch] = hz;   // row 512 half
            }
        }
    }

    #pragma unroll
    for (int i = tid; i < 512; i += 128) sh_h[i] = hG[i];

    // sh_x[a][i] = radon[batch][(i+257)&511][w0+a]; float4 covers 4 angles.
    const float* rb = radon + (size_t)batch * H * W;
    for (int i = tid; i < 1028; i += 128) {
        const int hsrc = (i + 257) & 511;
        const float4 v = *reinterpret_cast<const float4*>(rb + (size_t)hsrc * W + w0);
        sh_x[0][i] = v.x; sh_x[1][i] = v.y; sh_x[2][i] = v.z; sh_x[3][i] = v.w;
    }
    __syncthreads();

    const int h0 = tid * 4;

    float acc[4][4];
    #pragma unroll
    for (int a = 0; a < 4; a++)
        #pragma unroll
        for (int j = 0; j < 4; j++) acc[a][j] = 0.0f;

    float wn[4][8];
    #pragma unroll
    for (int a = 0; a < 4; a++) {
        const float4 v0 = *reinterpret_cast<const float4*>(&sh_x[a][h0]);
        const float4 v1 = *reinterpret_cast<const float4*>(&sh_x[a][h0 + 4]);
        wn[a][0] = v0.x; wn[a][1] = v0.y; wn[a][2] = v0.z; wn[a][3] = v0.w;
        wn[a][4] = v1.x; wn[a][5] = v1.y; wn[a][6] = v1.z; wn[a][7] = v1.w;
    }

    #pragma unroll 2
    for (int k = 0; k < 512; k += 4) {
        const float4 hv = *reinterpret_cast<const float4*>(&sh_h[k]);
        const float hvv[4] = {hv.x, hv.y, hv.z, hv.w};
        #pragma unroll
        for (int a = 0; a < 4; a++) {
            #pragma unroll
            for (int s = 0; s < 4; s++) {
                #pragma unroll
                for (int j = 0; j < 4; j++)
                    acc[a][j] = fmaf(hvv[s], wn[a][s + j], acc[a][j]);
            }
            const float4 nv = *reinterpret_cast<const float4*>(&sh_x[a][h0 + k + 8]);
            wn[a][0] = wn[a][4]; wn[a][1] = wn[a][5];
            wn[a][2] = wn[a][6]; wn[a][3] = wn[a][7];
            wn[a][4] = nv.x; wn[a][5] = nv.y; wn[a][6] = nv.z; wn[a][7] = nv.w;
        }
    }

    // Store duplicated fp16: row r -> entry (r+128) slot [batch]
    //                              -> entry (r+127) slot [4+batch]
    #pragma unroll
    for (int a = 0; a < 4; a++) {
        __half* col = reinterpret_cast<__half*>(g_F2 + (size_t)(w0 + a) * PADROWS);
        #pragma unroll
        for (int j = 0; j < 4; j++) {
            const int r = h0 + j;
            const __half hv = __float2half(acc[a][j]);
            col[(size_t)(r + 128) * 8 + batch]     = hv;
            col[(size_t)(r + 127) * 8 + 4 + batch] = hv;
        }
    }
}

// ---------------------------------------------------------------------------
// Kernel 2: backprojection. Two i-pixels per thread; one LDG.128 per
// (pixel, angle); HFMA2 interpolation with fp32 accumulation.
//   py = 255.5 + (j-256)*A_w + (i-256)*B_w;  py(i+1) = py(i) + B_w
// Entry half2 view: h2[0]=(b0,b1)row0, h2[1]=(b2,b3)row0,
//                   h2[2]=(b0,b1)row1, h2[3]=(b2,b3)row1
// ---------------------------------------------------------------------------
__global__ __launch_bounds__(256) void backproj_kernel(
    float* __restrict__ out)          // [NB][D][D]
{
    __shared__ float2 sAB[W];

    const int tid = threadIdx.y * 32 + threadIdx.x;
    for (int k = tid; k < W; k += 256) sAB[k] = g_AB[k];
    __syncthreads();

    const int j  = blockIdx.x * 32 + threadIdx.x;
    const int i0 = blockIdx.y * 16 + threadIdx.y * 2;   // pixels i0, i0+1

    const float xA = (float)(j - 256);
    const float yB = (float)(i0 - 256);

    // fp32 accumulators: [pixel][batch]
    float acc[2][4] = {{0.f,0.f,0.f,0.f},{0.f,0.f,0.f,0.f}};

    const uint4* Fw = g_F2 + 128;     // padding offset: entry = y0 + 128
    const __half2 one2 = __floats2half2_rn(1.0f, 1.0f);

    #pragma unroll 2
    for (int w = 0; w < W; ++w) {
        const float2 AB = sAB[w];
        const float py0 = fmaf(xA, AB.x, fmaf(yB, AB.y, 255.5f));
        const float py1 = py0 + AB.y;

        float pys[2] = {py0, py1};
        union { uint4 u; __half2 h2[4]; } pk[2];
        float fy[2];

        #pragma unroll
        for (int q = 0; q < 2; q++) {
            const float yf = floorf(pys[q]);
            fy[q] = pys[q] - yf;
            const int y0 = (int)yf;          // in [-107, 617]
            pk[q].u = __ldg(Fw + (ptrdiff_t)y0);
        }

        #pragma unroll
        for (int q = 0; q < 2; q++) {
            const __half2 fyh = __float2half2_rn(fy[q]);
            const __half2 w0h = __hsub2(one2, fyh);
            const __half2 va = __hfma2(pk[q].h2[2], fyh, __hmul2(pk[q].h2[0], w0h));
            const __half2 vb = __hfma2(pk[q].h2[3], fyh, __hmul2(pk[q].h2[1], w0h));
            acc[q][0] += __low2float(va);
            acc[q][1] += __high2float(va);
            acc[q][2] += __low2float(vb);
            acc[q][3] += __high2float(vb);
        }

        Fw += PADROWS;
    }

    const float s = (float)(M_PI / (2.0 * (double)W));
    #pragma unroll
    for (int q = 0; q < 2; q++) {
        const size_t p = (size_t)(i0 + q) * D + j;
        out[p]                 = acc[q][0] * s;
        out[p + (size_t)D*D]   = acc[q][1] * s;
        out[p + 2*(size_t)D*D] = acc[q][2] * s;
        out[p + 3*(size_t)D*D] = acc[q][3] * s;
    }
}

// ---------------------------------------------------------------------------
extern "C" void kernel_launch(void* const* d_in, const int* in_sizes, int n_in,
                              void* d_out, int out_size)
{
    const float* radon = nullptr;
    const float* hg    = nullptr;
    for (int k = 0; k < n_in; k++) {
        const int sz = in_sizes[k];
        if (sz == NB * H * W) radon = (const float*)d_in[k];
        else if (sz == H)     hg    = (const float*)d_in[k];
        // t_y (W*D*D) not needed: computed analytically.
    }

    filter_kernel<<<360, 128>>>(radon, hg);

    dim3 grid(D / 32, D / 16);
    dim3 block(32, 8);
    backproj_kernel<<<grid, block>>>((float*)d_out);
}